// round 10
// baseline (speedup 1.0000x reference)
#include <cuda_runtime.h>
#include <cuda_bf16.h>
#include <cstdint>
#include <math.h>

// Problem constants (fixed by the dataset)
#define NROWS   25000     // xN == yN
#define KPAIRS  8000
#define XD      100
#define YD      120
#define HID     100
#define NBT     196       // ceil(25000/128) B tiles (even — loop unrolls by 2)
#define NAT     63        // ceil(8000/128)  A tiles

// ======================= PTX helpers (sm_80+ only — no 'a' features) ========
__device__ __forceinline__ uint32_t smem_to_u32(const void* p) {
    uint32_t a;
    asm("{ .reg .u64 t; cvta.to.shared.u64 t, %1; cvt.u32.u64 %0, t; }" : "=r"(a) : "l"(p));
    return a;
}
__device__ __forceinline__ void cp_async16(uint32_t dst, const void* src) {
    asm volatile("cp.async.cg.shared.global [%0], [%1], 16;" :: "r"(dst), "l"(src));
}
#define CP_ASYNC_COMMIT() asm volatile("cp.async.commit_group;" ::: "memory")
#define CP_ASYNC_WAIT0()  asm volatile("cp.async.wait_group 0;" ::: "memory")

__device__ __forceinline__ void ldmatrix4(uint32_t* r, uint32_t addr) {
    asm volatile("ldmatrix.sync.aligned.m8n8.x4.shared.b16 {%0,%1,%2,%3}, [%4];"
                 : "=r"(r[0]), "=r"(r[1]), "=r"(r[2]), "=r"(r[3]) : "r"(addr));
}
__device__ __forceinline__ void mma_bf16(float* c, const uint32_t* a, uint32_t b0, uint32_t b1) {
    asm volatile("mma.sync.aligned.m16n8k16.row.col.f32.bf16.bf16.f32 "
                 "{%0,%1,%2,%3}, {%4,%5,%6,%7}, {%8,%9}, {%0,%1,%2,%3};"
                 : "+f"(c[0]), "+f"(c[1]), "+f"(c[2]), "+f"(c[3])
                 : "r"(a[0]), "r"(a[1]), "r"(a[2]), "r"(a[3]), "r"(b0), "r"(b1));
}

// 128x128 bf16 tile layout: row stride 256B, 16B-chunk XOR swizzle for
// conflict-free ldmatrix. chunk index k8 in 0..15.
__device__ __forceinline__ uint32_t tile_off(int r, int k8) {
    return (uint32_t)r * 256u + ((uint32_t)(k8 ^ (r & 7)) << 4);
}
__device__ __forceinline__ uint32_t pack_bf2(float a, float b) {
    __nv_bfloat162 t = __floats2bfloat162_rn(a, b);
    return *reinterpret_cast<uint32_t*>(&t);
}

// ---------------- scratch (device globals; no allocations allowed) ----------
__device__ float  g_x_mapped[NROWS * YD];   // f(x): 25000 x 120
__device__ float  g_y_mapped[NROWS * XD];   // g(y): 25000 x 100
__device__ double g_acc[8];                 // 0:cyc_fx 1:cyc_gy 2:sup_x 3:sup_y 4:fx_mis 5:gy_mis
__device__ uint4  g_B_sw[2ull * NBT * 2048];   // pre-swizzled bf16 B tiles (per problem)
__device__ uint4  g_A_sw[2ull * NAT * 2048];   // pre-swizzled gathered A tiles
__device__ float  g_b2[2][NBT * 128];          // padded rows = 1e30
__device__ float  g_a2[2][NAT * 128];

// ---------------- prep B: zero g_acc + bf16 swizzled tiles + row norms -------
// 16 threads per row (one 16B chunk each); 16-lane shfl reduce -> b2.
__global__ __launch_bounds__(256)
void prep_B_kernel(const float* __restrict__ yw, const float* __restrict__ xw)
{
    if (blockIdx.x == 0 && blockIdx.y == 0 && threadIdx.x < 8)
        g_acc[threadIdx.x] = 0.0;

    const int sel = blockIdx.y;
    const float* src = sel ? xw : yw;
    const int D = sel ? XD : YD;

    int t    = blockIdx.x * 256 + threadIdx.x;   // grid covers exactly NBT*128*16
    int k8   = t & 15;
    int r    = (t >> 4) & 127;
    int tile = t >> 11;
    int n    = tile * 128 + r;

    float f[8];
    float s = 0.0f;
    #pragma unroll
    for (int i = 0; i < 8; i++) {
        int k = k8 * 8 + i;
        f[i] = (n < NROWS && k < D) ? src[n * D + k] : 0.0f;
        s = fmaf(f[i], f[i], s);
    }
    uint4 v;
    v.x = pack_bf2(f[0], f[1]); v.y = pack_bf2(f[2], f[3]);
    v.z = pack_bf2(f[4], f[5]); v.w = pack_bf2(f[6], f[7]);
    uint4* base = g_B_sw + ((size_t)sel * NBT + tile) * 2048;
    base[tile_off(r, k8) >> 4] = v;

    #pragma unroll
    for (int off = 8; off; off >>= 1) s += __shfl_down_sync(0xffffffffu, s, off, 16);
    if (k8 == 0) g_b2[sel][n] = (n < NROWS) ? s : 1e30f;
}

// ---------------- fused MLP + cycle kernel (float4-vectorized inner loops) ---
template<int DIN, int DMID>
__global__ __launch_bounds__(128)
void mlp_cycle_kernel(const float* __restrict__ X,
                      const float* __restrict__ W1, const float* __restrict__ B1,
                      const float* __restrict__ W2, const float* __restrict__ B2,
                      const float* __restrict__ G1, const float* __restrict__ GB1,
                      const float* __restrict__ G2, const float* __restrict__ GB2,
                      int slot)
{
    constexpr int R = 8;
    __shared__ __align__(16) float s_in [R][DIN];
    __shared__ __align__(16) float s_h  [R][HID];
    __shared__ __align__(16) float s_mid[R][DMID];
    __shared__ __align__(16) float s_h2 [R][HID];
    __shared__ float s_red[R][4];

    float* mapped = (DMID == YD) ? g_x_mapped : g_y_mapped;

    const int tid  = threadIdx.x;
    const int base = blockIdx.x * R;

    for (int t = tid; t < R * DIN; t += 128)
        ((float*)s_in)[t] = X[base * DIN + t];
    __syncthreads();

    const int j = tid;
    float acc[R];

    // stage 1: h = relu(x @ W1 + B1)   (DIN -> HID)
    if (j < HID) {
        #pragma unroll
        for (int r = 0; r < R; r++) acc[r] = B1[j];
        for (int k4 = 0; k4 < DIN / 4; k4++) {
            const float w0 = W1[(4 * k4 + 0) * HID + j];
            const float w1 = W1[(4 * k4 + 1) * HID + j];
            const float w2 = W1[(4 * k4 + 2) * HID + j];
            const float w3 = W1[(4 * k4 + 3) * HID + j];
            #pragma unroll
            for (int r = 0; r < R; r++) {
                float4 a = *(const float4*)&s_in[r][4 * k4];
                float v = fmaf(a.x, w0, acc[r]);
                v = fmaf(a.y, w1, v);
                v = fmaf(a.z, w2, v);
                acc[r] = fmaf(a.w, w3, v);
            }
        }
        #pragma unroll
        for (int r = 0; r < R; r++) s_h[r][j] = fmaxf(acc[r], 0.0f);
    }
    __syncthreads();

    // stage 2: mid = h @ W2 + B2   (HID -> DMID), store mapped
    if (j < DMID) {
        #pragma unroll
        for (int r = 0; r < R; r++) acc[r] = B2[j];
        for (int k4 = 0; k4 < HID / 4; k4++) {
            const float w0 = W2[(4 * k4 + 0) * DMID + j];
            const float w1 = W2[(4 * k4 + 1) * DMID + j];
            const float w2 = W2[(4 * k4 + 2) * DMID + j];
            const float w3 = W2[(4 * k4 + 3) * DMID + j];
            #pragma unroll
            for (int r = 0; r < R; r++) {
                float4 a = *(const float4*)&s_h[r][4 * k4];
                float v = fmaf(a.x, w0, acc[r]);
                v = fmaf(a.y, w1, v);
                v = fmaf(a.z, w2, v);
                acc[r] = fmaf(a.w, w3, v);
            }
        }
        #pragma unroll
        for (int r = 0; r < R; r++) {
            s_mid[r][j] = acc[r];
            mapped[(base + r) * DMID + j] = acc[r];
        }
    }
    __syncthreads();

    // stage 3: h2 = relu(mid @ G1 + GB1)   (DMID -> HID)
    if (j < HID) {
        #pragma unroll
        for (int r = 0; r < R; r++) acc[r] = GB1[j];
        for (int k4 = 0; k4 < DMID / 4; k4++) {
            const float w0 = G1[(4 * k4 + 0) * HID + j];
            const float w1 = G1[(4 * k4 + 1) * HID + j];
            const float w2 = G1[(4 * k4 + 2) * HID + j];
            const float w3 = G1[(4 * k4 + 3) * HID + j];
            #pragma unroll
            for (int r = 0; r < R; r++) {
                float4 a = *(const float4*)&s_mid[r][4 * k4];
                float v = fmaf(a.x, w0, acc[r]);
                v = fmaf(a.y, w1, v);
                v = fmaf(a.z, w2, v);
                acc[r] = fmaf(a.w, w3, v);
            }
        }
        #pragma unroll
        for (int r = 0; r < R; r++) s_h2[r][j] = fmaxf(acc[r], 0.0f);
    }
    __syncthreads();

    // stage 4: rt = h2 @ G2 + GB2   (HID -> DIN), diff vs input
    float d2[R];
    if (j < DIN) {
        #pragma unroll
        for (int r = 0; r < R; r++) acc[r] = GB2[j];
        for (int k4 = 0; k4 < HID / 4; k4++) {
            const float w0 = G2[(4 * k4 + 0) * DIN + j];
            const float w1 = G2[(4 * k4 + 1) * DIN + j];
            const float w2 = G2[(4 * k4 + 2) * DIN + j];
            const float w3 = G2[(4 * k4 + 3) * DIN + j];
            #pragma unroll
            for (int r = 0; r < R; r++) {
                float4 a = *(const float4*)&s_h2[r][4 * k4];
                float v = fmaf(a.x, w0, acc[r]);
                v = fmaf(a.y, w1, v);
                v = fmaf(a.z, w2, v);
                acc[r] = fmaf(a.w, w3, v);
            }
        }
        #pragma unroll
        for (int r = 0; r < R; r++) {
            float d = acc[r] - s_in[r][j];
            d2[r] = d * d;
        }
    } else {
        #pragma unroll
        for (int r = 0; r < R; r++) d2[r] = 0.0f;
    }

    const int lane = tid & 31, wid = tid >> 5;
    #pragma unroll
    for (int r = 0; r < R; r++) {
        float v = d2[r];
        #pragma unroll
        for (int off = 16; off; off >>= 1)
            v += __shfl_down_sync(0xffffffffu, v, off);
        if (lane == 0) s_red[r][wid] = v;
    }
    __syncthreads();
    if (tid == 0) {
        double total = 0.0;
        #pragma unroll
        for (int r = 0; r < R; r++) {
            float v = s_red[r][0] + s_red[r][1] + s_red[r][2] + s_red[r][3];
            total += (double)sqrtf(v);
        }
        atomicAdd(&g_acc[slot], total);
    }
}

// ---------------- prep A: gathered bf16 tiles + query norms ------------------
__global__ __launch_bounds__(256)
void prep_A_kernel(const int* __restrict__ imap)
{
    const int sel = blockIdx.y;
    const float* mapped = sel ? g_y_mapped : g_x_mapped;
    const int D = sel ? XD : YD;

    int t    = blockIdx.x * 256 + threadIdx.x;   // grid covers exactly NAT*128*16
    int k8   = t & 15;
    int r    = (t >> 4) & 127;
    int tile = t >> 11;
    int q    = tile * 128 + r;
    int qq   = (q < KPAIRS) ? q : (KPAIRS - 1);
    int n    = imap[qq * 2 + sel];

    float f[8];
    float s = 0.0f;
    #pragma unroll
    for (int i = 0; i < 8; i++) {
        int k = k8 * 8 + i;
        f[i] = (k < D) ? mapped[n * D + k] : 0.0f;
        s = fmaf(f[i], f[i], s);
    }
    uint4 v;
    v.x = pack_bf2(f[0], f[1]); v.y = pack_bf2(f[2], f[3]);
    v.z = pack_bf2(f[4], f[5]); v.w = pack_bf2(f[6], f[7]);
    uint4* base = g_A_sw + ((size_t)sel * NAT + tile) * 2048;
    base[tile_off(r, k8) >> 4] = v;

    #pragma unroll
    for (int off = 8; off; off >>= 1) s += __shfl_down_sync(0xffffffffu, s, off, 16);
    if (k8 == 0) g_a2[sel][q] = s;   // padded q >= KPAIRS never read
}

// ---------------- supervised alignment terms (unchanged) ---------------------
__global__ __launch_bounds__(256)
void sup_kernel(const float* __restrict__ xw, const float* __restrict__ yw,
                const int* __restrict__ imap)
{
    __shared__ float sx[8], sy[8];
    const int tid   = threadIdx.x;
    const int lane  = tid & 31;
    const int warp  = tid >> 5;
    const int pair  = blockIdx.x * 8 + warp;

    float rx = 0.0f, ry = 0.0f;
    if (pair < KPAIRS) {
        const int xi = imap[pair * 2 + 0];
        const int yi = imap[pair * 2 + 1];
        float s = 0.0f;
        for (int k = lane; k < YD; k += 32) {
            float d = g_x_mapped[xi * YD + k] - yw[yi * YD + k];
            s = fmaf(d, d, s);
        }
        #pragma unroll
        for (int off = 16; off; off >>= 1) s += __shfl_down_sync(0xffffffffu, s, off);
        rx = sqrtf(s);

        float s2 = 0.0f;
        for (int k = lane; k < XD; k += 32) {
            float d = g_y_mapped[yi * XD + k] - xw[xi * XD + k];
            s2 = fmaf(d, d, s2);
        }
        #pragma unroll
        for (int off = 16; off; off >>= 1) s2 += __shfl_down_sync(0xffffffffu, s2, off);
        ry = sqrtf(s2);
    }
    if (lane == 0) { sx[warp] = rx; sy[warp] = ry; }
    __syncthreads();
    if (tid == 0) {
        double ax = 0.0, ay = 0.0;
        #pragma unroll
        for (int w = 0; w < 8; w++) { ax += (double)sx[w]; ay += (double)sy[w]; }
        atomicAdd(&g_acc[2], ax);
        atomicAdd(&g_acc[3], ay);
    }
}

// ---------------- mma.sync 1-NN kernel (deferred epilogue) --------------------
// grid (NAT, 2); 256 threads = 8 warps, 4(M) x 2(N). Each warp: 32M x 64N.
// Accumulators ping-pong (loop unrolled x2 -> compile-time buffers). The
// epilogue of tile t-1 follows the MMA issue of tile t, so FSETP/FFMA fill
// HMMA shadows. A fragments reloaded per tile from SMEM (frees 64 regs for
// the second accumulator). b2 lives in a 4-slot SMEM ring: copies write slot
// (t+1)&3, deferred epilogue reads (t-1)&3 — always disjoint, barrier-ordered.
static constexpr uint32_t OFF_A   = 0;                 // 32768
static constexpr uint32_t OFF_B   = 32768;             // 2 x 32768
static constexpr uint32_t OFF_B2  = 32768 + 65536;     // 4 x 512 ring
static constexpr uint32_t OFF_SV  = OFF_B2 + 2048;     // 128 x 2 floats
static constexpr uint32_t OFF_SI  = OFF_SV + 1024;     // 128 x 2 ints
static constexpr uint32_t NN_SMEM = OFF_SI + 1024;     // 102400 bytes

__device__ __forceinline__ void nn_epilogue(
    const float (&acc)[2][8][4], int te, const float* sb2ring,
    int wn, int tg, float (&runv)[4], int (&runi)[4])
{
    const float* b2t = sb2ring + (te & 3) * 128;
    const int colb = te * 128 + wn * 64 + tg * 2;
    #pragma unroll
    for (int nt = 0; nt < 8; nt++) {
        float2 b2p = *(const float2*)(b2t + wn * 64 + nt * 8 + tg * 2);
        const int c0 = colb + nt * 8;
        #pragma unroll
        for (int mt = 0; mt < 2; mt++) {
            const int ra = mt * 2, rb = mt * 2 + 1;
            float s0 = fmaf(-2.0f, acc[mt][nt][0], b2p.x);
            float s1 = fmaf(-2.0f, acc[mt][nt][1], b2p.y);
            float s2 = fmaf(-2.0f, acc[mt][nt][2], b2p.x);
            float s3 = fmaf(-2.0f, acc[mt][nt][3], b2p.y);
            if (s0 < runv[ra]) { runv[ra] = s0; runi[ra] = c0; }
            if (s1 < runv[ra]) { runv[ra] = s1; runi[ra] = c0 + 1; }
            if (s2 < runv[rb]) { runv[rb] = s2; runi[rb] = c0; }
            if (s3 < runv[rb]) { runv[rb] = s3; runi[rb] = c0 + 1; }
        }
    }
}

__device__ __forceinline__ void nn_step(
    int t, uint32_t smem_base, const float* sb2ring,
    const uint4* __restrict__ Bsrc, const float* __restrict__ b2src,
    int tid, int lane, int wm, int wn, int tg,
    float (&cur)[2][8][4], float (&prev)[2][8][4],
    float (&runv)[4], int (&runi)[4], bool do_epi)
{
    const int l7     = lane & 7;
    const int a_roff = ((lane >> 3) & 1) * 8 + l7;
    const int a_cpar = (lane >> 4) & 1;
    const int b_roff = ((lane >> 4) & 1) * 8 + l7;
    const int b_cpar = (lane >> 3) & 1;

    if (t > 0) {                       // wait for B tile t (issued in step t-1)
        CP_ASYNC_WAIT0();
        __syncthreads();
    }
    // issue copies for tile t+1 (B data -> buf (t+1)&1, b2 -> ring (t+1)&3)
    if (t + 1 < NBT) {
        const uint32_t dstB = smem_base + OFF_B + (uint32_t)((t + 1) & 1) * 32768u;
        const uint4* srcB = Bsrc + (size_t)(t + 1) * 2048;
        #pragma unroll
        for (int i = 0; i < 8; i++) {
            int c = tid + i * 256;
            cp_async16(dstB + c * 16, srcB + c);
        }
        if (tid < 32)
            cp_async16(smem_base + OFF_B2 + (uint32_t)((t + 1) & 3) * 512u + tid * 16,
                       (const uint4*)(b2src + (t + 1) * 128) + tid);
        CP_ASYNC_COMMIT();
    }

    // zero current accumulators
    #pragma unroll
    for (int mt = 0; mt < 2; mt++)
        #pragma unroll
        for (int nt = 0; nt < 8; nt++)
            #pragma unroll
            for (int e = 0; e < 4; e++) cur[mt][nt][e] = 0.0f;

    // MMA for tile t (A fragments reloaded from resident SMEM A tile)
    const uint32_t bbuf = smem_base + OFF_B + (uint32_t)(t & 1) * 32768u;
    const uint32_t b_rowbyte = (uint32_t)(wn * 64 + b_roff) * 256u;
    const uint32_t arow0 = smem_base + OFF_A + (uint32_t)(wm * 32 + a_roff) * 256u;
    #pragma unroll
    for (int ks = 0; ks < 8; ks++) {
        const uint32_t koff_b = ((uint32_t)((2 * ks + b_cpar) ^ l7) << 4);
        const uint32_t koff_a = ((uint32_t)((2 * ks + a_cpar) ^ l7) << 4);
        uint32_t bfr[4][4];
        #pragma unroll
        for (int p = 0; p < 4; p++)
            ldmatrix4(bfr[p], bbuf + b_rowbyte + (uint32_t)(p * 16) * 256u + koff_b);
        uint32_t afr[2][4];
        #pragma unroll
        for (int mt = 0; mt < 2; mt++)
            ldmatrix4(afr[mt], arow0 + (uint32_t)(mt * 16) * 256u + koff_a);
        #pragma unroll
        for (int mt = 0; mt < 2; mt++)
            #pragma unroll
            for (int nt = 0; nt < 8; nt++)
                mma_bf16(cur[mt][nt], afr[mt],
                         bfr[nt >> 1][(nt & 1) * 2 + 0],
                         bfr[nt >> 1][(nt & 1) * 2 + 1]);
    }

    // deferred epilogue for tile t-1 (overlaps tensor pipe of tile t)
    if (do_epi)
        nn_epilogue(prev, t - 1, sb2ring, wn, tg, runv, runi);
}

__global__ __launch_bounds__(256, 1)
void nn_mma_kernel(const int* __restrict__ imap)
{
    extern __shared__ char smem[];
    __shared__ float sred[8];

    const uint32_t smem_base = smem_to_u32(smem);
    const int tid   = threadIdx.x;
    const int lane  = tid & 31;
    const int warp  = tid >> 5;
    const int wm    = warp >> 1;       // 0..3  -> rows wm*32
    const int wn    = warp & 1;        // 0..1  -> cols wn*64
    const int g     = lane >> 2;
    const int tg    = lane & 3;
    const int tileA = blockIdx.x;
    const int sel   = blockIdx.y;
    const int abase = tileA * 128;

    const float* sb2ring = (const float*)(smem + OFF_B2);
    float* sval = (float*)(smem + OFF_SV);
    int*   sidx = (int*)  (smem + OFF_SI);

    const uint4* Asrc = g_A_sw + ((size_t)sel * NAT + tileA) * 2048;
    const uint4* Bsrc = g_B_sw + (size_t)sel * NBT * 2048;
    const float* b2src = g_b2[sel];

    // ---- prologue: async-copy A tile + B tile 0 + b2 ring slot 0 ----
    #pragma unroll
    for (int i = 0; i < 8; i++) {
        int c = tid + i * 256;
        cp_async16(smem_base + OFF_A + c * 16, Asrc + c);
        cp_async16(smem_base + OFF_B + c * 16, Bsrc + c);
    }
    if (tid < 32) cp_async16(smem_base + OFF_B2 + tid * 16, (const uint4*)b2src + tid);
    CP_ASYNC_COMMIT();
    CP_ASYNC_WAIT0();
    __syncthreads();

    float runv[4];
    int   runi[4];
    #pragma unroll
    for (int i = 0; i < 4; i++) { runv[i] = 1e38f; runi[i] = 0x7fffffff; }

    float accA[2][8][4], accB[2][8][4];

    for (int t = 0; t < NBT; t += 2) {
        nn_step(t,     smem_base, sb2ring, Bsrc, b2src, tid, lane, wm, wn, tg,
                accA, accB, runv, runi, t > 0);
        nn_step(t + 1, smem_base, sb2ring, Bsrc, b2src, tid, lane, wm, wn, tg,
                accB, accA, runv, runi, true);
    }
    // final epilogue: tile NBT-1 lives in accB (NBT even)
    nn_epilogue(accB, NBT - 1, sb2ring, wn, tg, runv, runi);
    __syncthreads();

    // ---- reduce mins: intra quad (tg lanes), then across the two N warps ----
    #pragma unroll
    for (int r = 0; r < 4; r++) {
        float v  = runv[r];
        int   bi = runi[r];
        #pragma unroll
        for (int m = 1; m <= 2; m <<= 1) {
            float ov = __shfl_xor_sync(0xffffffffu, v,  m);
            int   oi = __shfl_xor_sync(0xffffffffu, bi, m);
            if (ov < v || (ov == v && oi < bi)) { v = ov; bi = oi; }
        }
        if (tg == 0) {
            int row = wm * 32 + (r >> 1) * 16 + (r & 1) * 8 + g;   // 0..127
            sval[row * 2 + wn] = v;
            sidx[row * 2 + wn] = bi;
        }
    }
    __syncthreads();

    // ---- final per-row combine + mismatch contribution ----
    float contrib = 0.0f;
    if (tid < 128) {
        float v0 = sval[tid * 2 + 0], v1 = sval[tid * 2 + 1];
        int   i0 = sidx[tid * 2 + 0], i1 = sidx[tid * 2 + 1];
        float v = v0; int bi = i0;
        if (v1 < v || (v1 == v && i1 < bi)) { v = v1; bi = i1; }
        const int q = abase + tid;
        if (q < KPAIRS) {
            float d2 = g_a2[sel][q] + v;
            float dist = sqrtf(fmaxf(d2, 0.0f));
            int gidx = imap[q * 2 + sel];
            if (bi != gidx) contrib = ceilf(dist) - floorf(dist);
        }
    }
    #pragma unroll
    for (int off = 16; off; off >>= 1)
        contrib += __shfl_down_sync(0xffffffffu, contrib, off);
    if (lane == 0) sred[warp] = contrib;
    __syncthreads();
    if (tid == 0) {
        double s = 0.0;
        #pragma unroll
        for (int w = 0; w < 8; w++) s += (double)sred[w];
        atomicAdd(&g_acc[4 + sel], s);
    }
}

// ---------------- combine ------------------------------------------------------
__global__ void combine_kernel(float* __restrict__ out)
{
    if (threadIdx.x == 0) {
        double v = (g_acc[0] + g_acc[1]) / (double)NROWS
                 + (g_acc[2] + g_acc[3] + g_acc[4] + g_acc[5]) / (double)KPAIRS;
        out[0] = (float)v;
    }
}

// ---------------- launch -------------------------------------------------------
// Launch order chosen so nn_mma_kernel is launch #6 (profiled by ncu -s 5 -c 1).
extern "C" void kernel_launch(void* const* d_in, const int* in_sizes, int n_in,
                              void* d_out, int out_size)
{
    const float* xw    = (const float*)d_in[0];
    const float* yw    = (const float*)d_in[1];
    const float* fx_w1 = (const float*)d_in[2];
    const float* fx_b1 = (const float*)d_in[3];
    const float* fx_w2 = (const float*)d_in[4];
    const float* fx_b2 = (const float*)d_in[5];
    const float* gy_w1 = (const float*)d_in[6];
    const float* gy_b1 = (const float*)d_in[7];
    const float* gy_w2 = (const float*)d_in[8];
    const float* gy_b2 = (const float*)d_in[9];
    const int*   imap  = (const int*)d_in[10];
    float* out = (float*)d_out;

    cudaFuncSetAttribute(nn_mma_kernel,
                         cudaFuncAttributeMaxDynamicSharedMemorySize, (int)NN_SMEM);

    // #1: zero accumulators + B tiles/norms for both problems
    prep_B_kernel<<<dim3(NBT * 128 * 16 / 256, 2), 256>>>(yw, xw);

    // #2, #3: MLP cycles (produce g_x_mapped / g_y_mapped)
    mlp_cycle_kernel<XD, YD><<<NROWS / 8, 128>>>(
        xw, fx_w1, fx_b1, fx_w2, fx_b2, gy_w1, gy_b1, gy_w2, gy_b2, 0);
    mlp_cycle_kernel<YD, XD><<<NROWS / 8, 128>>>(
        yw, gy_w1, gy_b1, gy_w2, gy_b2, fx_w1, fx_b1, fx_w2, fx_b2, 1);

    // #4: gathered A tiles + query norms for both problems
    prep_A_kernel<<<dim3(NAT * 128 * 16 / 256, 2), 256>>>(imap);

    // #5: supervised terms
    sup_kernel<<<KPAIRS / 8, 256>>>(xw, yw, imap);

    // #6: both 1-NN mismatch problems on tensor cores
    nn_mma_kernel<<<dim3(NAT, 2), 256, NN_SMEM>>>(imap);

    // #7: combine
    combine_kernel<<<1, 32>>>(out);
}

// round 11
// speedup vs baseline: 1.6450x; 1.6450x over previous
#include <cuda_runtime.h>
#include <cuda_bf16.h>
#include <cstdint>
#include <math.h>

// Problem constants (fixed by the dataset)
#define NROWS   25000     // xN == yN
#define KPAIRS  8000
#define XD      100
#define YD      120
#define HID     100
#define NBT     196       // ceil(25000/128) B tiles
#define NAT     63        // ceil(8000/128)  A tiles

// ======================= PTX helpers (sm_80+ only — no 'a' features) ========
__device__ __forceinline__ uint32_t smem_to_u32(const void* p) {
    uint32_t a;
    asm("{ .reg .u64 t; cvta.to.shared.u64 t, %1; cvt.u32.u64 %0, t; }" : "=r"(a) : "l"(p));
    return a;
}
__device__ __forceinline__ void cp_async16(uint32_t dst, const void* src) {
    asm volatile("cp.async.cg.shared.global [%0], [%1], 16;" :: "r"(dst), "l"(src));
}
#define CP_ASYNC_COMMIT() asm volatile("cp.async.commit_group;" ::: "memory")
#define CP_ASYNC_WAIT0()  asm volatile("cp.async.wait_group 0;" ::: "memory")

__device__ __forceinline__ void ldmatrix4(uint32_t* r, uint32_t addr) {
    asm volatile("ldmatrix.sync.aligned.m8n8.x4.shared.b16 {%0,%1,%2,%3}, [%4];"
                 : "=r"(r[0]), "=r"(r[1]), "=r"(r[2]), "=r"(r[3]) : "r"(addr));
}
__device__ __forceinline__ void mma_bf16(float* c, const uint32_t* a, uint32_t b0, uint32_t b1) {
    asm volatile("mma.sync.aligned.m16n8k16.row.col.f32.bf16.bf16.f32 "
                 "{%0,%1,%2,%3}, {%4,%5,%6,%7}, {%8,%9}, {%0,%1,%2,%3};"
                 : "+f"(c[0]), "+f"(c[1]), "+f"(c[2]), "+f"(c[3])
                 : "r"(a[0]), "r"(a[1]), "r"(a[2]), "r"(a[3]), "r"(b0), "r"(b1));
}

// 128x128 bf16 tile layout: row stride 256B, 16B-chunk XOR swizzle for
// conflict-free ldmatrix. chunk index k8 in 0..15.
__device__ __forceinline__ uint32_t tile_off(int r, int k8) {
    return (uint32_t)r * 256u + ((uint32_t)(k8 ^ (r & 7)) << 4);
}
__device__ __forceinline__ uint32_t pack_bf2(float a, float b) {
    __nv_bfloat162 t = __floats2bfloat162_rn(a, b);
    return *reinterpret_cast<uint32_t*>(&t);
}

// ---------------- scratch (device globals; no allocations allowed) ----------
__device__ float  g_x_mapped[NROWS * YD];   // f(x): 25000 x 120
__device__ float  g_y_mapped[NROWS * XD];   // g(y): 25000 x 100
__device__ double g_acc[8];                 // 0:cyc_fx 1:cyc_gy 2:sup_x 3:sup_y 4:fx_mis 5:gy_mis
__device__ uint4  g_B_sw[2ull * NBT * 2048];   // pre-swizzled bf16 B tiles (per problem)
__device__ uint4  g_A_sw[2ull * NAT * 2048];   // pre-swizzled gathered A tiles
__device__ float  g_b2[2][NBT * 128];          // padded rows = 1e30
__device__ float  g_a2[2][NAT * 128];

// ---------------- prep B: zero g_acc + bf16 swizzled tiles + row norms -------
// 16 threads per row (one 16B chunk each); 16-lane shfl reduce -> b2.
__global__ __launch_bounds__(256)
void prep_B_kernel(const float* __restrict__ yw, const float* __restrict__ xw)
{
    if (blockIdx.x == 0 && blockIdx.y == 0 && threadIdx.x < 8)
        g_acc[threadIdx.x] = 0.0;

    const int sel = blockIdx.y;
    const float* src = sel ? xw : yw;
    const int D = sel ? XD : YD;

    int t    = blockIdx.x * 256 + threadIdx.x;   // grid covers exactly NBT*128*16
    int k8   = t & 15;
    int r    = (t >> 4) & 127;
    int tile = t >> 11;
    int n    = tile * 128 + r;

    float f[8];
    float s = 0.0f;
    #pragma unroll
    for (int i = 0; i < 8; i++) {
        int k = k8 * 8 + i;
        f[i] = (n < NROWS && k < D) ? src[n * D + k] : 0.0f;
        s = fmaf(f[i], f[i], s);
    }
    uint4 v;
    v.x = pack_bf2(f[0], f[1]); v.y = pack_bf2(f[2], f[3]);
    v.z = pack_bf2(f[4], f[5]); v.w = pack_bf2(f[6], f[7]);
    uint4* base = g_B_sw + ((size_t)sel * NBT + tile) * 2048;
    base[tile_off(r, k8) >> 4] = v;

    #pragma unroll
    for (int off = 8; off; off >>= 1) s += __shfl_down_sync(0xffffffffu, s, off, 16);
    if (k8 == 0) g_b2[sel][n] = (n < NROWS) ? s : 1e30f;
}

// ---------------- fused MLP + cycle kernel (float4-vectorized inner loops) ---
template<int DIN, int DMID>
__global__ __launch_bounds__(128)
void mlp_cycle_kernel(const float* __restrict__ X,
                      const float* __restrict__ W1, const float* __restrict__ B1,
                      const float* __restrict__ W2, const float* __restrict__ B2,
                      const float* __restrict__ G1, const float* __restrict__ GB1,
                      const float* __restrict__ G2, const float* __restrict__ GB2,
                      int slot)
{
    constexpr int R = 8;
    __shared__ __align__(16) float s_in [R][DIN];
    __shared__ __align__(16) float s_h  [R][HID];
    __shared__ __align__(16) float s_mid[R][DMID];
    __shared__ __align__(16) float s_h2 [R][HID];
    __shared__ float s_red[R][4];

    float* mapped = (DMID == YD) ? g_x_mapped : g_y_mapped;

    const int tid  = threadIdx.x;
    const int base = blockIdx.x * R;

    for (int t = tid; t < R * DIN; t += 128)
        ((float*)s_in)[t] = X[base * DIN + t];
    __syncthreads();

    const int j = tid;
    float acc[R];

    // stage 1: h = relu(x @ W1 + B1)   (DIN -> HID)
    if (j < HID) {
        #pragma unroll
        for (int r = 0; r < R; r++) acc[r] = B1[j];
        for (int k4 = 0; k4 < DIN / 4; k4++) {
            const float w0 = W1[(4 * k4 + 0) * HID + j];
            const float w1 = W1[(4 * k4 + 1) * HID + j];
            const float w2 = W1[(4 * k4 + 2) * HID + j];
            const float w3 = W1[(4 * k4 + 3) * HID + j];
            #pragma unroll
            for (int r = 0; r < R; r++) {
                float4 a = *(const float4*)&s_in[r][4 * k4];
                float v = fmaf(a.x, w0, acc[r]);
                v = fmaf(a.y, w1, v);
                v = fmaf(a.z, w2, v);
                acc[r] = fmaf(a.w, w3, v);
            }
        }
        #pragma unroll
        for (int r = 0; r < R; r++) s_h[r][j] = fmaxf(acc[r], 0.0f);
    }
    __syncthreads();

    // stage 2: mid = h @ W2 + B2   (HID -> DMID), store mapped
    if (j < DMID) {
        #pragma unroll
        for (int r = 0; r < R; r++) acc[r] = B2[j];
        for (int k4 = 0; k4 < HID / 4; k4++) {
            const float w0 = W2[(4 * k4 + 0) * DMID + j];
            const float w1 = W2[(4 * k4 + 1) * DMID + j];
            const float w2 = W2[(4 * k4 + 2) * DMID + j];
            const float w3 = W2[(4 * k4 + 3) * DMID + j];
            #pragma unroll
            for (int r = 0; r < R; r++) {
                float4 a = *(const float4*)&s_h[r][4 * k4];
                float v = fmaf(a.x, w0, acc[r]);
                v = fmaf(a.y, w1, v);
                v = fmaf(a.z, w2, v);
                acc[r] = fmaf(a.w, w3, v);
            }
        }
        #pragma unroll
        for (int r = 0; r < R; r++) {
            s_mid[r][j] = acc[r];
            mapped[(base + r) * DMID + j] = acc[r];
        }
    }
    __syncthreads();

    // stage 3: h2 = relu(mid @ G1 + GB1)   (DMID -> HID)
    if (j < HID) {
        #pragma unroll
        for (int r = 0; r < R; r++) acc[r] = GB1[j];
        for (int k4 = 0; k4 < DMID / 4; k4++) {
            const float w0 = G1[(4 * k4 + 0) * HID + j];
            const float w1 = G1[(4 * k4 + 1) * HID + j];
            const float w2 = G1[(4 * k4 + 2) * HID + j];
            const float w3 = G1[(4 * k4 + 3) * HID + j];
            #pragma unroll
            for (int r = 0; r < R; r++) {
                float4 a = *(const float4*)&s_mid[r][4 * k4];
                float v = fmaf(a.x, w0, acc[r]);
                v = fmaf(a.y, w1, v);
                v = fmaf(a.z, w2, v);
                acc[r] = fmaf(a.w, w3, v);
            }
        }
        #pragma unroll
        for (int r = 0; r < R; r++) s_h2[r][j] = fmaxf(acc[r], 0.0f);
    }
    __syncthreads();

    // stage 4: rt = h2 @ G2 + GB2   (HID -> DIN), diff vs input
    float d2[R];
    if (j < DIN) {
        #pragma unroll
        for (int r = 0; r < R; r++) acc[r] = GB2[j];
        for (int k4 = 0; k4 < HID / 4; k4++) {
            const float w0 = G2[(4 * k4 + 0) * DIN + j];
            const float w1 = G2[(4 * k4 + 1) * DIN + j];
            const float w2 = G2[(4 * k4 + 2) * DIN + j];
            const float w3 = G2[(4 * k4 + 3) * DIN + j];
            #pragma unroll
            for (int r = 0; r < R; r++) {
                float4 a = *(const float4*)&s_h2[r][4 * k4];
                float v = fmaf(a.x, w0, acc[r]);
                v = fmaf(a.y, w1, v);
                v = fmaf(a.z, w2, v);
                acc[r] = fmaf(a.w, w3, v);
            }
        }
        #pragma unroll
        for (int r = 0; r < R; r++) {
            float d = acc[r] - s_in[r][j];
            d2[r] = d * d;
        }
    } else {
        #pragma unroll
        for (int r = 0; r < R; r++) d2[r] = 0.0f;
    }

    const int lane = tid & 31, wid = tid >> 5;
    #pragma unroll
    for (int r = 0; r < R; r++) {
        float v = d2[r];
        #pragma unroll
        for (int off = 16; off; off >>= 1)
            v += __shfl_down_sync(0xffffffffu, v, off);
        if (lane == 0) s_red[r][wid] = v;
    }
    __syncthreads();
    if (tid == 0) {
        double total = 0.0;
        #pragma unroll
        for (int r = 0; r < R; r++) {
            float v = s_red[r][0] + s_red[r][1] + s_red[r][2] + s_red[r][3];
            total += (double)sqrtf(v);
        }
        atomicAdd(&g_acc[slot], total);
    }
}

// ---------------- prep A: gathered bf16 tiles + query norms ------------------
__global__ __launch_bounds__(256)
void prep_A_kernel(const int* __restrict__ imap)
{
    const int sel = blockIdx.y;
    const float* mapped = sel ? g_y_mapped : g_x_mapped;
    const int D = sel ? XD : YD;

    int t    = blockIdx.x * 256 + threadIdx.x;   // grid covers exactly NAT*128*16
    int k8   = t & 15;
    int r    = (t >> 4) & 127;
    int tile = t >> 11;
    int q    = tile * 128 + r;
    int qq   = (q < KPAIRS) ? q : (KPAIRS - 1);
    int n    = imap[qq * 2 + sel];

    float f[8];
    float s = 0.0f;
    #pragma unroll
    for (int i = 0; i < 8; i++) {
        int k = k8 * 8 + i;
        f[i] = (k < D) ? mapped[n * D + k] : 0.0f;
        s = fmaf(f[i], f[i], s);
    }
    uint4 v;
    v.x = pack_bf2(f[0], f[1]); v.y = pack_bf2(f[2], f[3]);
    v.z = pack_bf2(f[4], f[5]); v.w = pack_bf2(f[6], f[7]);
    uint4* base = g_A_sw + ((size_t)sel * NAT + tile) * 2048;
    base[tile_off(r, k8) >> 4] = v;

    #pragma unroll
    for (int off = 8; off; off >>= 1) s += __shfl_down_sync(0xffffffffu, s, off, 16);
    if (k8 == 0) g_a2[sel][q] = s;   // padded q >= KPAIRS never read
}

// ---------------- supervised alignment terms ---------------------------------
__global__ __launch_bounds__(256)
void sup_kernel(const float* __restrict__ xw, const float* __restrict__ yw,
                const int* __restrict__ imap)
{
    __shared__ float sx[8], sy[8];
    const int tid   = threadIdx.x;
    const int lane  = tid & 31;
    const int warp  = tid >> 5;
    const int pair  = blockIdx.x * 8 + warp;

    float rx = 0.0f, ry = 0.0f;
    if (pair < KPAIRS) {
        const int xi = imap[pair * 2 + 0];
        const int yi = imap[pair * 2 + 1];
        float s = 0.0f;
        for (int k = lane; k < YD; k += 32) {
            float d = g_x_mapped[xi * YD + k] - yw[yi * YD + k];
            s = fmaf(d, d, s);
        }
        #pragma unroll
        for (int off = 16; off; off >>= 1) s += __shfl_down_sync(0xffffffffu, s, off);
        rx = sqrtf(s);

        float s2 = 0.0f;
        for (int k = lane; k < XD; k += 32) {
            float d = g_y_mapped[yi * XD + k] - xw[xi * XD + k];
            s2 = fmaf(d, d, s2);
        }
        #pragma unroll
        for (int off = 16; off; off >>= 1) s2 += __shfl_down_sync(0xffffffffu, s2, off);
        ry = sqrtf(s2);
    }
    if (lane == 0) { sx[warp] = rx; sy[warp] = ry; }
    __syncthreads();
    if (tid == 0) {
        double ax = 0.0, ay = 0.0;
        #pragma unroll
        for (int w = 0; w < 8; w++) { ax += (double)sx[w]; ay += (double)sy[w]; }
        atomicAdd(&g_acc[2], ax);
        atomicAdd(&g_acc[3], ay);
    }
}

// ---------------- mma.sync 1-NN kernel (R8 structure — known good) -----------
// grid (NAT, 2); 256 threads = 8 warps in a 4(M) x 2(N) grid. Each warp owns
// 32 M-rows x 64 N-cols of the 128x128 block tile. A fragments live in
// registers for the entire 196-tile sweep; B tiles stream via cp.async
// double-buffering. Tracks min(b2 - 2*dot) per output row (a2 row-constant).
static constexpr uint32_t OFF_A   = 0;
static constexpr uint32_t OFF_B   = 32768;           // 2 x 32768
static constexpr uint32_t OFF_B2  = 32768 + 65536;   // 2 x 512
static constexpr uint32_t OFF_SV  = OFF_B2 + 1024;   // 128 x 2 floats
static constexpr uint32_t OFF_SI  = OFF_SV + 1024;   // 128 x 2 ints
static constexpr uint32_t NN_SMEM = OFF_SI + 1024;   // 101376 bytes

__global__ __launch_bounds__(256, 1)
void nn_mma_kernel(const int* __restrict__ imap)
{
    extern __shared__ char smem[];
    __shared__ float sred[8];

    const uint32_t smem_base = smem_to_u32(smem);
    const int tid   = threadIdx.x;
    const int lane  = tid & 31;
    const int warp  = tid >> 5;
    const int wm    = warp >> 1;       // 0..3  -> rows wm*32
    const int wn    = warp & 1;        // 0..1  -> cols wn*64
    const int l7    = lane & 7;
    const int g     = lane >> 2;       // output-row group within m16 tile
    const int tg    = lane & 3;        // column pair selector
    const int tileA = blockIdx.x;
    const int sel   = blockIdx.y;
    const int abase = tileA * 128;

    float* sb2  = (float*)(smem + OFF_B2);
    float* sval = (float*)(smem + OFF_SV);
    int*   sidx = (int*)  (smem + OFF_SI);

    const uint4* Asrc = g_A_sw + ((size_t)sel * NAT + tileA) * 2048;
    const uint4* Bsrc = g_B_sw + (size_t)sel * NBT * 2048;
    const float* b2src = g_b2[sel];

    // ---- prologue: async-copy A tile + B tile 0 + b2 tile 0 ----
    #pragma unroll
    for (int i = 0; i < 8; i++) {
        int c = tid + i * 256;
        cp_async16(smem_base + OFF_A + c * 16, Asrc + c);
        cp_async16(smem_base + OFF_B + c * 16, Bsrc + c);
    }
    if (tid < 32) cp_async16(smem_base + OFF_B2 + tid * 16, (const uint4*)b2src + tid);
    CP_ASYNC_COMMIT();
    CP_ASYNC_WAIT0();
    __syncthreads();

    // ---- preload all A fragments into registers (resident for whole sweep) ----
    const int a_roff = ((lane >> 3) & 1) * 8 + l7;
    const int a_cpar = (lane >> 4) & 1;
    uint32_t afr[2][8][4];
    #pragma unroll
    for (int mt = 0; mt < 2; mt++) {
        const uint32_t arow = (uint32_t)(wm * 32 + mt * 16 + a_roff);
        #pragma unroll
        for (int ks = 0; ks < 8; ks++) {
            uint32_t addr = smem_base + OFF_A + arow * 256u
                          + ((uint32_t)((2 * ks + a_cpar) ^ l7) << 4);
            ldmatrix4(afr[mt][ks], addr);
        }
    }

    const int b_roff = ((lane >> 4) & 1) * 8 + l7;
    const int b_cpar = (lane >> 3) & 1;
    const uint32_t b_rowbyte = (uint32_t)(wn * 64 + b_roff) * 256u;

    float runv[4];
    int   runi[4];
    #pragma unroll
    for (int i = 0; i < 4; i++) { runv[i] = 1e38f; runi[i] = 0x7fffffff; }

    for (int t = 0; t < NBT; ++t) {
        const int buf = t & 1;
        if (t > 0) {               // wait for B tile t (issued last iteration)
            CP_ASYNC_WAIT0();
            __syncthreads();
        }
        // issue B tile t+1 into the other buffer (overlaps compute of tile t)
        if (t + 1 < NBT) {
            const uint32_t dstB = smem_base + OFF_B + (uint32_t)(buf ^ 1) * 32768u;
            const uint4* srcB = Bsrc + (size_t)(t + 1) * 2048;
            #pragma unroll
            for (int i = 0; i < 8; i++) {
                int c = tid + i * 256;
                cp_async16(dstB + c * 16, srcB + c);
            }
            if (tid < 32)
                cp_async16(smem_base + OFF_B2 + (uint32_t)(buf ^ 1) * 512u + tid * 16,
                           (const uint4*)(b2src + (t + 1) * 128) + tid);
            CP_ASYNC_COMMIT();
        }

        // ---- compute 128x128 tile: 8 k-steps x (4 ldmatrix + 16 mma) ----
        const uint32_t bbuf = smem_base + OFF_B + (uint32_t)buf * 32768u;
        float acc[2][8][4];
        #pragma unroll
        for (int mt = 0; mt < 2; mt++)
            #pragma unroll
            for (int nt = 0; nt < 8; nt++)
                #pragma unroll
                for (int e = 0; e < 4; e++) acc[mt][nt][e] = 0.0f;

        #pragma unroll
        for (int ks = 0; ks < 8; ks++) {
            uint32_t koff = ((uint32_t)((2 * ks + b_cpar) ^ l7) << 4);
            uint32_t bfr[4][4];
            #pragma unroll
            for (int p = 0; p < 4; p++)
                ldmatrix4(bfr[p], bbuf + b_rowbyte + (uint32_t)(p * 16) * 256u + koff);
            #pragma unroll
            for (int mt = 0; mt < 2; mt++)
                #pragma unroll
                for (int nt = 0; nt < 8; nt++)
                    mma_bf16(acc[mt][nt], afr[mt][ks],
                             bfr[nt >> 1][(nt & 1) * 2 + 0],
                             bfr[nt >> 1][(nt & 1) * 2 + 1]);
        }

        // ---- epilogue: s = b2 - 2*dot ; running min with ascending cols ----
        const float* b2t = sb2 + buf * 128;
        const int colb = t * 128 + wn * 64 + tg * 2;
        #pragma unroll
        for (int nt = 0; nt < 8; nt++) {
            float2 b2p = *(const float2*)(b2t + wn * 64 + nt * 8 + tg * 2);
            const int c0 = colb + nt * 8;
            #pragma unroll
            for (int mt = 0; mt < 2; mt++) {
                const int ra = mt * 2, rb = mt * 2 + 1;
                float s0 = fmaf(-2.0f, acc[mt][nt][0], b2p.x);
                float s1 = fmaf(-2.0f, acc[mt][nt][1], b2p.y);
                float s2 = fmaf(-2.0f, acc[mt][nt][2], b2p.x);
                float s3 = fmaf(-2.0f, acc[mt][nt][3], b2p.y);
                if (s0 < runv[ra]) { runv[ra] = s0; runi[ra] = c0; }
                if (s1 < runv[ra]) { runv[ra] = s1; runi[ra] = c0 + 1; }
                if (s2 < runv[rb]) { runv[rb] = s2; runi[rb] = c0; }
                if (s3 < runv[rb]) { runv[rb] = s3; runi[rb] = c0 + 1; }
            }
        }
    }
    __syncthreads();

    // ---- reduce mins: intra quad (tg lanes), then across the two N warps ----
    #pragma unroll
    for (int r = 0; r < 4; r++) {
        float v  = runv[r];
        int   bi = runi[r];
        #pragma unroll
        for (int m = 1; m <= 2; m <<= 1) {
            float ov = __shfl_xor_sync(0xffffffffu, v,  m);
            int   oi = __shfl_xor_sync(0xffffffffu, bi, m);
            if (ov < v || (ov == v && oi < bi)) { v = ov; bi = oi; }
        }
        if (tg == 0) {
            int row = wm * 32 + (r >> 1) * 16 + (r & 1) * 8 + g;   // 0..127
            sval[row * 2 + wn] = v;
            sidx[row * 2 + wn] = bi;
        }
    }
    __syncthreads();

    // ---- final per-row combine + mismatch contribution ----
    float contrib = 0.0f;
    if (tid < 128) {
        float v0 = sval[tid * 2 + 0], v1 = sval[tid * 2 + 1];
        int   i0 = sidx[tid * 2 + 0], i1 = sidx[tid * 2 + 1];
        float v = v0; int bi = i0;
        if (v1 < v || (v1 == v && i1 < bi)) { v = v1; bi = i1; }
        const int q = abase + tid;
        if (q < KPAIRS) {
            float d2 = g_a2[sel][q] + v;
            float dist = sqrtf(fmaxf(d2, 0.0f));
            int gidx = imap[q * 2 + sel];
            if (bi != gidx) contrib = ceilf(dist) - floorf(dist);
        }
    }
    #pragma unroll
    for (int off = 16; off; off >>= 1)
        contrib += __shfl_down_sync(0xffffffffu, contrib, off);
    if (lane == 0) sred[warp] = contrib;
    __syncthreads();
    if (tid == 0) {
        double s = 0.0;
        #pragma unroll
        for (int w = 0; w < 8; w++) s += (double)sred[w];
        atomicAdd(&g_acc[4 + sel], s);
    }
}

// ---------------- combine ------------------------------------------------------
__global__ void combine_kernel(float* __restrict__ out)
{
    if (threadIdx.x == 0) {
        double v = (g_acc[0] + g_acc[1]) / (double)NROWS
                 + (g_acc[2] + g_acc[3] + g_acc[4] + g_acc[5]) / (double)KPAIRS;
        out[0] = (float)v;
    }
}

// ---------------- launch -------------------------------------------------------
// Launch order chosen so nn_mma_kernel is launch #6 (profiled by ncu -s 5 -c 1).
extern "C" void kernel_launch(void* const* d_in, const int* in_sizes, int n_in,
                              void* d_out, int out_size)
{
    const float* xw    = (const float*)d_in[0];
    const float* yw    = (const float*)d_in[1];
    const float* fx_w1 = (const float*)d_in[2];
    const float* fx_b1 = (const float*)d_in[3];
    const float* fx_w2 = (const float*)d_in[4];
    const float* fx_b2 = (const float*)d_in[5];
    const float* gy_w1 = (const float*)d_in[6];
    const float* gy_b1 = (const float*)d_in[7];
    const float* gy_w2 = (const float*)d_in[8];
    const float* gy_b2 = (const float*)d_in[9];
    const int*   imap  = (const int*)d_in[10];
    float* out = (float*)d_out;

    cudaFuncSetAttribute(nn_mma_kernel,
                         cudaFuncAttributeMaxDynamicSharedMemorySize, (int)NN_SMEM);

    // #1: zero accumulators + B tiles/norms for both problems
    prep_B_kernel<<<dim3(NBT * 128 * 16 / 256, 2), 256>>>(yw, xw);

    // #2, #3: MLP cycles (produce g_x_mapped / g_y_mapped)
    mlp_cycle_kernel<XD, YD><<<NROWS / 8, 128>>>(
        xw, fx_w1, fx_b1, fx_w2, fx_b2, gy_w1, gy_b1, gy_w2, gy_b2, 0);
    mlp_cycle_kernel<YD, XD><<<NROWS / 8, 128>>>(
        yw, gy_w1, gy_b1, gy_w2, gy_b2, fx_w1, fx_b1, fx_w2, fx_b2, 1);

    // #4: gathered A tiles + query norms for both problems
    prep_A_kernel<<<dim3(NAT * 128 * 16 / 256, 2), 256>>>(imap);

    // #5: supervised terms
    sup_kernel<<<KPAIRS / 8, 256>>>(xw, yw, imap);

    // #6: both 1-NN mismatch problems on tensor cores (R8 known-good kernel)
    nn_mma_kernel<<<dim3(NAT, 2), 256, NN_SMEM>>>(imap);

    // #7: combine
    combine_kernel<<<1, 32>>>(out);
}